// round 15
// baseline (speedup 1.0000x reference)
#include <cuda_runtime.h>
#include <cuda_bf16.h>
#include <cuda_fp16.h>
#include <stdint.h>
#include <math.h>

// Problem constants
#define BB 4
#define CC 256
#define HH 80
#define WW 80
#define KK9 9
#define HW (HH*WW)
#define NPOS (BB*HW)             // 25600
#define NKB 36                   // K chunks: 9 taps x 4 chunks of 64 channels

// Scratch (device globals; no allocation allowed)
__device__ __align__(16) float    g_xp[NPOS*CC];      // pooled input NHWC (fp32)
__device__ __align__(16) uint32_t g_xph[NPOS*CC/2];   // fp16 image, 2ch/u32
__device__ __align__(16) float    g_tmp[NPOS*CC];     // horizontal pool sums (NCHW)
__device__ __align__(16) float    g_om[NPOS*32];      // per-pos offsets(18)+mask(9)
__device__ __align__(16) uint2 g_wf[NKB*4*32*32];     // deform W frags [kb][khalf][ntile][lane]
__device__ __align__(16) uint2 g_wfo[NKB*4*4*32];     // offmask W frags [kb][khalf][ntile(4)][lane]

// ============================ helpers ============================
__device__ __forceinline__ uint32_t smem_u32(const void* p) {
    uint32_t a;
    asm("{ .reg .u64 t; cvta.to.shared.u64 t, %1; cvt.u32.u64 %0, t; }" : "=r"(a) : "l"(p));
    return a;
}

__device__ __forceinline__ void ldsm4(uint32_t& a0, uint32_t& a1, uint32_t& a2,
                                      uint32_t& a3, uint32_t addr) {
    asm volatile("ldmatrix.sync.aligned.m8n8.x4.shared.b16 {%0,%1,%2,%3}, [%4];"
        : "=r"(a0), "=r"(a1), "=r"(a2), "=r"(a3) : "r"(addr));
}

__device__ __forceinline__ void mma16816(float* d, uint32_t a0, uint32_t a1,
                                         uint32_t a2, uint32_t a3,
                                         uint32_t b0, uint32_t b1) {
    asm volatile("mma.sync.aligned.m16n8k16.row.col.f32.f16.f16.f32 "
        "{%0,%1,%2,%3}, {%4,%5,%6,%7}, {%8,%9}, {%0,%1,%2,%3};"
        : "+f"(d[0]), "+f"(d[1]), "+f"(d[2]), "+f"(d[3])
        : "r"(a0), "r"(a1), "r"(a2), "r"(a3), "r"(b0), "r"(b1));
}

// pack two floats as fp16x2: low half = a, high half = b
__device__ __forceinline__ uint32_t pack_f16(float a, float b) {
    uint32_t r;
    asm("cvt.rn.f16x2.f32 %0, %1, %2;" : "=r"(r) : "f"(b), "f"(a));
    return r;
}

// ---------------------------------------------------------------------------
// Kernel 1a: horizontal 3-sum (NCHW -> g_tmp NCHW)
// ---------------------------------------------------------------------------
__global__ void pool_h(const float* __restrict__ x) {
    int i = blockIdx.x * 256 + threadIdx.x;
    int w = i % WW;
    float s = x[i];
    if (w > 0)      s += x[i-1];
    if (w < WW-1)   s += x[i+1];
    g_tmp[i] = s;
}

// ---------------------------------------------------------------------------
// Kernel 1b: vertical 3-sum + /9 + transpose to NHWC (g_tmp -> g_xp)
// Also emits the fp16 image g_xph (2 channels packed per u32).
// ---------------------------------------------------------------------------
__global__ void pool_v() {
    __shared__ float tile[16][17];
    int id = blockIdx.x;
    int c0 = (id & 15) * 16; id >>= 4;
    int w0 = (id % 5) * 16;  id /= 5;
    int h  = id % HH;
    int b  = id / HH;
    int t  = threadIdx.x;
    int ci = t >> 4, wi = t & 15;
    int c = c0 + ci, wcol = w0 + wi;
    const float* xb = g_tmp + (b*CC + c) * HW;
    float s = 0.f;
#pragma unroll
    for (int dy = -1; dy <= 1; dy++) {
        int y = h + dy;
        if (y < 0 || y >= HH) continue;
        s += xb[y*WW + wcol];
    }
    tile[ci][wi] = s * (1.f/9.f);
    __syncthreads();
    int wi2 = t >> 4, ci2 = t & 15;
    int pos = (b*HH + h)*WW + w0 + wi2;
    float v0 = tile[ci2][wi2];
    g_xp[pos*CC + c0 + ci2] = v0;
    if ((ci2 & 1) == 0) {
        float v1 = tile[ci2+1][wi2];
        g_xph[(pos*CC + c0 + ci2) >> 1] = pack_f16(v0, v1);
    }
}

// ---------------------------------------------------------------------------
// Kernel 2: weight prep — fp16 B fragments for mma.m16n8k16.row.col
// ---------------------------------------------------------------------------
#define NWF  (NKB*4*32*32)       // 147456 uint2 records
#define NWFO (NKB*4*4*32)        // 18432 uint2 records
__global__ void wprep_kernel(const float* __restrict__ off_w,
                             const float* __restrict__ mod_w,
                             const float* __restrict__ w) {
    int i = blockIdx.x * 256 + threadIdx.x;
    if (i < NWF) {
        int j = i;
        int lane  = j & 31;
        int nt    = (j >> 5) & 31;
        int khalf = (j >> 10) & 3;
        int kb    = j >> 12;
        int kk = kb >> 2;
        int o  = nt*8 + (lane >> 2);
        int c0 = (kb & 3)*64 + khalf*16 + 2*(lane & 3);
        float wv[4];
#pragma unroll
        for (int q = 0; q < 4; q++) {
            int c = c0 + (q >> 1)*8 + (q & 1);
            wv[q] = w[(o*CC + c)*KK9 + kk];
        }
        uint2 rec;
        rec.x = pack_f16(wv[0], wv[1]);
        rec.y = pack_f16(wv[2], wv[3]);
        g_wf[j] = rec;
    } else if (i < NWF + NWFO) {
        int j = i - NWF;
        int lane  = j & 31;
        int nt    = (j >> 5) & 3;
        int khalf = (j >> 7) & 3;
        int kb    = j >> 9;
        int kk = kb >> 2;
        int o  = nt*8 + (lane >> 2);
        int c0 = (kb & 3)*64 + khalf*16 + 2*(lane & 3);
        float wv[4];
#pragma unroll
        for (int q = 0; q < 4; q++) {
            int c = c0 + (q >> 1)*8 + (q & 1);
            float f = 0.f;
            if (o < 18)      f = off_w[(o*CC + c)*KK9 + kk];
            else if (o < 27) f = mod_w[((o-18)*CC + c)*KK9 + kk];
            wv[q] = f;
        }
        uint2 rec;
        rec.x = pack_f16(wv[0], wv[1]);
        rec.y = pack_f16(wv[2], wv[3]);
        g_wfo[j] = rec;
    }
}

// ---------------------------------------------------------------------------
// Kernel 3: offset+mask conv via mma.sync fp16, full-tap phases (K=256).
// Block: 256 thr = 8 warps (2m x 4n). M=32 pos, N=32(27). Grid 800. 9 syncs.
// (unchanged — measured 43.6 us)
// ---------------------------------------------------------------------------
__device__ __forceinline__ void om_gather(char* sA, const int* sBase, int tap,
                                          int buf, int t) {
    const uint4* xph4 = (const uint4*)g_xph;
    int p = t >> 3, g = t & 7;
    int pos = sBase[tap*32 + p];
    char* Ab = sA + buf*16384;
    int off = p*128 + ((g*16) ^ ((p & 7) << 4));
#pragma unroll
    for (int c4 = 0; c4 < 4; c4++) {
        uint4 hp = make_uint4(0u, 0u, 0u, 0u);
        if (pos >= 0) hp = xph4[pos*32 + c4*8 + g];
        *(uint4*)(Ab + c4*4096 + off) = hp;
    }
}

__global__ void __launch_bounds__(256) offmask_kernel(const float* __restrict__ off_b,
                                                      const float* __restrict__ mod_b) {
    __shared__ __align__(16) char sA[2*16384];
    __shared__ int sBase[288];
    uint32_t sb = smem_u32(sA);

    int t = threadIdx.x, lane = t & 31, wid = t >> 5;
    int wm = wid >> 2, wn = wid & 3;       // 2m x 4n
    int pbase = blockIdx.x * 32;

    for (int q = t; q < 288; q += 256) {
        int tap = q >> 5, p = q & 31;
        int pgl = pbase + p;
        int b = pgl / HW, r = pgl % HW;
        int h = r / WW, w = r % WW;
        int y = h - 1 + tap/3, x = w - 1 + tap%3;
        sBase[q] = (((unsigned)y < HH) && ((unsigned)x < WW))
                   ? ((b*HH + y)*WW + x) : -1;
    }
    __syncthreads();

    om_gather(sA, sBase, 0, 0, t);
    __syncthreads();

    float acc[4] = {0.f, 0.f, 0.f, 0.f};

    int rowterm = (wm*16 + (lane & 15)) * 128;
    int kterm = ((lane >> 4) & 1) * 16;
    int swzl = (lane & 7) << 4;

    for (int tap = 0; tap < 9; tap++) {
        int buf = tap & 1;
        if (tap + 1 < 9) om_gather(sA, sBase, tap + 1, buf ^ 1, t);

#pragma unroll 1
        for (int c4 = 0; c4 < 4; c4++) {
            uint32_t Ah = sb + buf*16384 + c4*4096;
            const uint2* gb = g_wfo + (size_t)(tap*4 + c4)*4*4*32 + wn*32 + lane;
#pragma unroll
            for (int s = 0; s < 4; s++) {
                uint2 bf = gb[(s*4) * 32];
                int off = (s*32 + kterm) ^ swzl;
                uint32_t a0, a1, a2, a3;
                ldsm4(a0, a1, a2, a3, Ah + rowterm + off);
                mma16816(acc, a0, a1, a2, a3, bf.x, bf.y);
            }
        }
        __syncthreads();
    }

    // epilogue: bias / 2*sigmoid, direct stores to g_om
    int row = pbase + wm*16 + (lane >> 2);
    int col = wn*8 + 2*(lane & 3);
#pragma unroll
    for (int q = 0; q < 4; q++) {
        int cc = col + (q & 1);
        int rr = row + (q >> 1)*8;
        float v = acc[q];
        if (cc < 18)      v = v + off_b[cc];
        else if (cc < 27) v = 2.f / (1.f + expf(-(v + mod_b[cc-18])));
        else continue;
        g_om[rr*32 + cc] = v;
    }
}

// ---------------------------------------------------------------------------
// Kernel 4: deformable conv via mma.sync fp16, full-tap phases (K=256).
// Block: 256 thr = 8 warps (2m x 4n), M=64 pos, N=256. Grid 400. 9 syncs.
// Warp tile 32m x 64n: each B fragment feeds TWO row-halves (halves B L2 traffic).
// Dynamic smem 83 KB -> 2 blocks/SM.
// ---------------------------------------------------------------------------
#define DSM_A    0        // 2 x 32768 A bufs; epilogue [256][64] f32 = 64 KB
#define DSM_CW   65536    // float4[576] = 9216
#define DSM_CI   74752    // int4[576]   = 9216
#define DSM_OB   83968    // int[64]
#define DSM_BIAS 84224    // float[256]
#define DSM_TOT  85248

__device__ __forceinline__ void deform_gather(char* dsm, int tap, int buf, int t) {
    const float4* xp4 = (const float4*)g_xp;
    const float4* sCW = (const float4*)(dsm + DSM_CW);
    const int4*   sCI = (const int4*)(dsm + DSM_CI);
    char* Ab = dsm + DSM_A + buf*32768;
#pragma unroll
    for (int it = 0; it < 2; it++) {
        int task = t + it*256;                 // 512 tasks: 64 pos x 8 groups
        int p = task >> 3, g = task & 7;
        float4 bw = sCW[tap*64 + p];
        int4 iv = sCI[tap*64 + p];
        int off = p*128 + ((g*16) ^ ((p & 7) << 4));
#pragma unroll
        for (int c4 = 0; c4 < 4; c4++) {
            float v[8];
            int fbase = c4*16 + g*2;
#pragma unroll
            for (int j = 0; j < 2; j++) {
                int f = fbase + j;
                float4 a  = xp4[iv.x + f];
                float4 b2 = xp4[iv.y + f];
                float4 c2 = xp4[iv.z + f];
                float4 d2 = xp4[iv.w + f];
                v[4*j+0] = bw.x*a.x + bw.y*b2.x + bw.z*c2.x + bw.w*d2.x;
                v[4*j+1] = bw.x*a.y + bw.y*b2.y + bw.z*c2.y + bw.w*d2.y;
                v[4*j+2] = bw.x*a.z + bw.y*b2.z + bw.z*c2.z + bw.w*d2.z;
                v[4*j+3] = bw.x*a.w + bw.y*b2.w + bw.z*c2.w + bw.w*d2.w;
            }
            uint4 hp;
            hp.x = pack_f16(v[0], v[1]);
            hp.y = pack_f16(v[2], v[3]);
            hp.z = pack_f16(v[4], v[5]);
            hp.w = pack_f16(v[6], v[7]);
            *(uint4*)(Ab + c4*8192 + off) = hp;
        }
    }
}

__global__ void __launch_bounds__(256, 2) deform_kernel(const float* __restrict__ bias,
                                                        float* __restrict__ out) {
    extern __shared__ __align__(16) char dsm[];
    float4* sCW = (float4*)(dsm + DSM_CW);
    int4*   sCI = (int4*)(dsm + DSM_CI);
    int*    sOB = (int*)(dsm + DSM_OB);
    float*  sBias = (float*)(dsm + DSM_BIAS);
    uint32_t sb = smem_u32(dsm);

    int t = threadIdx.x, lane = t & 31, wid = t >> 5;
    int wm = wid >> 2, wn = wid & 3;    // 2 mgroups (32m) x 4 ngroups (64n)
    int pbase = blockIdx.x * 64;

    // corners for all 9 taps (576 = 9 x 64)
    for (int q = t; q < 576; q += 256) {
        int tap = q >> 6, p = q & 63;
        int pgl = pbase + p;
        int b = pgl / HW, r = pgl % HW;
        int h = r / WW, w = r % WW;
        float dy = g_om[pgl*32 + 2*tap];
        float dx = g_om[pgl*32 + 2*tap + 1];
        float m  = g_om[pgl*32 + 18 + tap];
        float py = (float)(h - 1 + tap/3) + dy;
        float px = (float)(w - 1 + tap%3) + dx;
        float fy = floorf(py), fx = floorf(px);
        int y0 = (int)fy, x0 = (int)fx;
        float wy = py - fy, wx = px - fx;
        int y1 = y0 + 1, x1 = x0 + 1;
        bool vy0 = (unsigned)y0 < HH, vy1 = (unsigned)y1 < HH;
        bool vx0 = (unsigned)x0 < WW, vx1 = (unsigned)x1 < WW;
        float4 wv;
        wv.x = (1.f-wy)*(1.f-wx)*m * (float)(vy0 && vx0);
        wv.y = (1.f-wy)*wx      *m * (float)(vy0 && vx1);
        wv.z = wy*(1.f-wx)      *m * (float)(vy1 && vx0);
        wv.w = wy*wx            *m * (float)(vy1 && vx1);
        int yc0 = min(max(y0, 0), HH-1), yc1 = min(max(y1, 0), HH-1);
        int xc0 = min(max(x0, 0), WW-1), xc1 = min(max(x1, 0), WW-1);
        int rowb = b*HH;
        int4 iv;
        iv.x = ((rowb + yc0)*WW + xc0) * (CC/4);
        iv.y = ((rowb + yc0)*WW + xc1) * (CC/4);
        iv.z = ((rowb + yc1)*WW + xc0) * (CC/4);
        iv.w = ((rowb + yc1)*WW + xc1) * (CC/4);
        sCW[q] = wv;
        sCI[q] = iv;
    }
    if (t < 64) {
        int pgl = pbase + t;
        sOB[t] = (pgl / HW) * (CC*HW) + (pgl % HW);
    }
    sBias[t] = bias[t];
    __syncthreads();

    deform_gather(dsm, 0, 0, t);
    __syncthreads();

    float acc[2][8][4];
#pragma unroll
    for (int hf = 0; hf < 2; hf++)
#pragma unroll
        for (int nt = 0; nt < 8; nt++)
#pragma unroll
            for (int q = 0; q < 4; q++) acc[hf][nt][q] = 0.f;

    int m0 = wm * 32;
    int rowA = (m0 + (lane & 15)) * 128;
    int kterm = ((lane >> 4) & 1) * 16;
    int swzl = (lane & 7) << 4;

    for (int tap = 0; tap < 9; tap++) {
        int buf = tap & 1;
        if (tap + 1 < 9) deform_gather(dsm, tap + 1, buf ^ 1, t);

#pragma unroll 1
        for (int c4 = 0; c4 < 4; c4++) {
            uint32_t Ah = sb + buf*32768 + c4*8192;
            const uint2* gbase = g_wf + ((size_t)(tap*4 + c4)*4*32 + wn*8) * 32 + lane;
#pragma unroll
            for (int h = 0; h < 4; h++) {
                uint2 bf[8];
#pragma unroll
                for (int nt = 0; nt < 8; nt++)
                    bf[nt] = gbase[(h*32 + nt) * 32];
                int off = (h*32 + kterm) ^ swzl;
                uint32_t a0, a1, a2, a3;
                ldsm4(a0, a1, a2, a3, Ah + rowA + off);
#pragma unroll
                for (int nt = 0; nt < 8; nt++)
                    mma16816(acc[0][nt], a0, a1, a2, a3, bf[nt].x, bf[nt].y);
                ldsm4(a0, a1, a2, a3, Ah + rowA + 2048 + off);   // rows m0+16..m0+31
#pragma unroll
                for (int nt = 0; nt < 8; nt++)
                    mma16816(acc[1][nt], a0, a1, a2, a3, bf[nt].x, bf[nt].y);
            }
        }
        __syncthreads();
    }

    // epilogue: acc -> smem (reuse A region) -> coalesced NCHW stores
    float* sEp = (float*)(dsm + DSM_A);   // [o][m] = [256][64]
    int rr = lane >> 2, cc = 2*(lane & 3);
#pragma unroll
    for (int hf = 0; hf < 2; hf++) {
#pragma unroll
        for (int nt = 0; nt < 8; nt++) {
            int n = wn*64 + nt*8 + cc;
            int m = m0 + hf*16 + rr;
            sEp[n*64 + m]         = acc[hf][nt][0];
            sEp[(n+1)*64 + m]     = acc[hf][nt][1];
            sEp[n*64 + m + 8]     = acc[hf][nt][2];
            sEp[(n+1)*64 + m + 8] = acc[hf][nt][3];
        }
    }
    __syncthreads();
#pragma unroll
    for (int i = 0; i < 64; i++) {
        int idx = i*256 + t;
        int m = idx & 63, o = idx >> 6;
        out[sOB[m] + o*HW] = sEp[idx] + sBias[o];
    }
}

// ---------------------------------------------------------------------------
extern "C" void kernel_launch(void* const* d_in, const int* in_sizes, int n_in,
                              void* d_out, int out_size) {
    const float* x     = (const float*)d_in[0];
    const float* off_w = (const float*)d_in[1];
    const float* off_b = (const float*)d_in[2];
    const float* mod_w = (const float*)d_in[3];
    const float* mod_b = (const float*)d_in[4];
    const float* w     = (const float*)d_in[5];
    const float* b     = (const float*)d_in[6];
    float* out = (float*)d_out;

    cudaFuncSetAttribute(deform_kernel,
                         cudaFuncAttributeMaxDynamicSharedMemorySize, DSM_TOT);

    pool_h<<<(NPOS*CC)/256, 256>>>(x);
    pool_v<<<BB*HH*5*16, 256>>>();
    wprep_kernel<<<(NWF + NWFO + 255)/256, 256>>>(off_w, mod_w, w);
    offmask_kernel<<<NPOS/32, 256>>>(off_b, mod_b);
    deform_kernel<<<NPOS/64, 256, DSM_TOT>>>(b, out);
}

// round 16
// speedup vs baseline: 1.2193x; 1.2193x over previous
#include <cuda_runtime.h>
#include <cuda_bf16.h>
#include <cuda_fp16.h>
#include <stdint.h>
#include <math.h>

// Problem constants
#define BB 4
#define CC 256
#define HH 80
#define WW 80
#define KK9 9
#define HW (HH*WW)
#define NPOS (BB*HW)             // 25600
#define NKB 36                   // K chunks: 9 taps x 4 chunks of 64 channels

// Scratch (device globals; no allocation allowed)
__device__ __align__(16) float    g_xp[NPOS*CC];      // pooled input NHWC (fp32)
__device__ __align__(16) uint32_t g_xph[NPOS*CC/2];   // fp16 image, 2ch/u32
__device__ __align__(16) float    g_tmp[NPOS*CC];     // horizontal pool sums (NCHW)
__device__ __align__(16) float    g_om[NPOS*32];      // per-pos offsets(18)+mask(9)
__device__ __align__(16) uint2 g_wf[NKB*4*32*32];     // deform W frags [kb][khalf][ntile][lane]
__device__ __align__(16) uint2 g_wfo[NKB*4*4*32];     // offmask W frags [kb][khalf][ntile(4)][lane]

// ============================ helpers ============================
__device__ __forceinline__ uint32_t smem_u32(const void* p) {
    uint32_t a;
    asm("{ .reg .u64 t; cvta.to.shared.u64 t, %1; cvt.u32.u64 %0, t; }" : "=r"(a) : "l"(p));
    return a;
}

__device__ __forceinline__ void ldsm4(uint32_t& a0, uint32_t& a1, uint32_t& a2,
                                      uint32_t& a3, uint32_t addr) {
    asm volatile("ldmatrix.sync.aligned.m8n8.x4.shared.b16 {%0,%1,%2,%3}, [%4];"
        : "=r"(a0), "=r"(a1), "=r"(a2), "=r"(a3) : "r"(addr));
}

__device__ __forceinline__ void mma16816(float* d, uint32_t a0, uint32_t a1,
                                         uint32_t a2, uint32_t a3,
                                         uint32_t b0, uint32_t b1) {
    asm volatile("mma.sync.aligned.m16n8k16.row.col.f32.f16.f16.f32 "
        "{%0,%1,%2,%3}, {%4,%5,%6,%7}, {%8,%9}, {%0,%1,%2,%3};"
        : "+f"(d[0]), "+f"(d[1]), "+f"(d[2]), "+f"(d[3])
        : "r"(a0), "r"(a1), "r"(a2), "r"(a3), "r"(b0), "r"(b1));
}

// pack two floats as fp16x2: low half = a, high half = b
__device__ __forceinline__ uint32_t pack_f16(float a, float b) {
    uint32_t r;
    asm("cvt.rn.f16x2.f32 %0, %1, %2;" : "=r"(r) : "f"(b), "f"(a));
    return r;
}

// fp16x2 lerp of 4 corners: r = a*w0 + b*w1 + c*w2 + d*w3
__device__ __forceinline__ uint32_t blend4_h2(uint32_t a, uint32_t b, uint32_t c,
                                              uint32_t d, uint32_t w0, uint32_t w1,
                                              uint32_t w2, uint32_t w3) {
    uint32_t r;
    asm("{\n\t"
        ".reg .b32 t;\n\t"
        "mul.rn.f16x2 t, %1, %5;\n\t"
        "fma.rn.f16x2 t, %2, %6, t;\n\t"
        "fma.rn.f16x2 t, %3, %7, t;\n\t"
        "fma.rn.f16x2 %0, %4, %8, t;\n\t"
        "}"
        : "=r"(r)
        : "r"(a), "r"(b), "r"(c), "r"(d), "r"(w0), "r"(w1), "r"(w2), "r"(w3));
    return r;
}

// ---------------------------------------------------------------------------
// Kernel 1a: horizontal 3-sum (NCHW -> g_tmp NCHW)
// ---------------------------------------------------------------------------
__global__ void pool_h(const float* __restrict__ x) {
    int i = blockIdx.x * 256 + threadIdx.x;
    int w = i % WW;
    float s = x[i];
    if (w > 0)      s += x[i-1];
    if (w < WW-1)   s += x[i+1];
    g_tmp[i] = s;
}

// ---------------------------------------------------------------------------
// Kernel 1b: vertical 3-sum + /9 + transpose to NHWC (g_tmp -> g_xp)
// Also emits the fp16 image g_xph (2 channels packed per u32).
// ---------------------------------------------------------------------------
__global__ void pool_v() {
    __shared__ float tile[16][17];
    int id = blockIdx.x;
    int c0 = (id & 15) * 16; id >>= 4;
    int w0 = (id % 5) * 16;  id /= 5;
    int h  = id % HH;
    int b  = id / HH;
    int t  = threadIdx.x;
    int ci = t >> 4, wi = t & 15;
    int c = c0 + ci, wcol = w0 + wi;
    const float* xb = g_tmp + (b*CC + c) * HW;
    float s = 0.f;
#pragma unroll
    for (int dy = -1; dy <= 1; dy++) {
        int y = h + dy;
        if (y < 0 || y >= HH) continue;
        s += xb[y*WW + wcol];
    }
    tile[ci][wi] = s * (1.f/9.f);
    __syncthreads();
    int wi2 = t >> 4, ci2 = t & 15;
    int pos = (b*HH + h)*WW + w0 + wi2;
    float v0 = tile[ci2][wi2];
    g_xp[pos*CC + c0 + ci2] = v0;
    if ((ci2 & 1) == 0) {
        float v1 = tile[ci2+1][wi2];
        g_xph[(pos*CC + c0 + ci2) >> 1] = pack_f16(v0, v1);
    }
}

// ---------------------------------------------------------------------------
// Kernel 2: weight prep — fp16 B fragments for mma.m16n8k16.row.col
// ---------------------------------------------------------------------------
#define NWF  (NKB*4*32*32)       // 147456 uint2 records
#define NWFO (NKB*4*4*32)        // 18432 uint2 records
__global__ void wprep_kernel(const float* __restrict__ off_w,
                             const float* __restrict__ mod_w,
                             const float* __restrict__ w) {
    int i = blockIdx.x * 256 + threadIdx.x;
    if (i < NWF) {
        int j = i;
        int lane  = j & 31;
        int nt    = (j >> 5) & 31;
        int khalf = (j >> 10) & 3;
        int kb    = j >> 12;
        int kk = kb >> 2;
        int o  = nt*8 + (lane >> 2);
        int c0 = (kb & 3)*64 + khalf*16 + 2*(lane & 3);
        float wv[4];
#pragma unroll
        for (int q = 0; q < 4; q++) {
            int c = c0 + (q >> 1)*8 + (q & 1);
            wv[q] = w[(o*CC + c)*KK9 + kk];
        }
        uint2 rec;
        rec.x = pack_f16(wv[0], wv[1]);
        rec.y = pack_f16(wv[2], wv[3]);
        g_wf[j] = rec;
    } else if (i < NWF + NWFO) {
        int j = i - NWF;
        int lane  = j & 31;
        int nt    = (j >> 5) & 3;
        int khalf = (j >> 7) & 3;
        int kb    = j >> 9;
        int kk = kb >> 2;
        int o  = nt*8 + (lane >> 2);
        int c0 = (kb & 3)*64 + khalf*16 + 2*(lane & 3);
        float wv[4];
#pragma unroll
        for (int q = 0; q < 4; q++) {
            int c = c0 + (q >> 1)*8 + (q & 1);
            float f = 0.f;
            if (o < 18)      f = off_w[(o*CC + c)*KK9 + kk];
            else if (o < 27) f = mod_w[((o-18)*CC + c)*KK9 + kk];
            wv[q] = f;
        }
        uint2 rec;
        rec.x = pack_f16(wv[0], wv[1]);
        rec.y = pack_f16(wv[2], wv[3]);
        g_wfo[j] = rec;
    }
}

// ---------------------------------------------------------------------------
// Kernel 3: offset+mask conv via mma.sync fp16, full-tap phases (K=256).
// Block: 256 thr = 8 warps (2m x 4n). M=32 pos, N=32(27). Grid 800. 9 syncs.
// (unchanged — measured 43.6 us)
// ---------------------------------------------------------------------------
__device__ __forceinline__ void om_gather(char* sA, const int* sBase, int tap,
                                          int buf, int t) {
    const uint4* xph4 = (const uint4*)g_xph;
    int p = t >> 3, g = t & 7;
    int pos = sBase[tap*32 + p];
    char* Ab = sA + buf*16384;
    int off = p*128 + ((g*16) ^ ((p & 7) << 4));
#pragma unroll
    for (int c4 = 0; c4 < 4; c4++) {
        uint4 hp = make_uint4(0u, 0u, 0u, 0u);
        if (pos >= 0) hp = xph4[pos*32 + c4*8 + g];
        *(uint4*)(Ab + c4*4096 + off) = hp;
    }
}

__global__ void __launch_bounds__(256) offmask_kernel(const float* __restrict__ off_b,
                                                      const float* __restrict__ mod_b) {
    __shared__ __align__(16) char sA[2*16384];
    __shared__ int sBase[288];
    uint32_t sb = smem_u32(sA);

    int t = threadIdx.x, lane = t & 31, wid = t >> 5;
    int wm = wid >> 2, wn = wid & 3;       // 2m x 4n
    int pbase = blockIdx.x * 32;

    for (int q = t; q < 288; q += 256) {
        int tap = q >> 5, p = q & 31;
        int pgl = pbase + p;
        int b = pgl / HW, r = pgl % HW;
        int h = r / WW, w = r % WW;
        int y = h - 1 + tap/3, x = w - 1 + tap%3;
        sBase[q] = (((unsigned)y < HH) && ((unsigned)x < WW))
                   ? ((b*HH + y)*WW + x) : -1;
    }
    __syncthreads();

    om_gather(sA, sBase, 0, 0, t);
    __syncthreads();

    float acc[4] = {0.f, 0.f, 0.f, 0.f};

    int rowterm = (wm*16 + (lane & 15)) * 128;
    int kterm = ((lane >> 4) & 1) * 16;
    int swzl = (lane & 7) << 4;

    for (int tap = 0; tap < 9; tap++) {
        int buf = tap & 1;
        if (tap + 1 < 9) om_gather(sA, sBase, tap + 1, buf ^ 1, t);

#pragma unroll 1
        for (int c4 = 0; c4 < 4; c4++) {
            uint32_t Ah = sb + buf*16384 + c4*4096;
            const uint2* gb = g_wfo + (size_t)(tap*4 + c4)*4*4*32 + wn*32 + lane;
#pragma unroll
            for (int s = 0; s < 4; s++) {
                uint2 bf = gb[(s*4) * 32];
                int off = (s*32 + kterm) ^ swzl;
                uint32_t a0, a1, a2, a3;
                ldsm4(a0, a1, a2, a3, Ah + rowterm + off);
                mma16816(acc, a0, a1, a2, a3, bf.x, bf.y);
            }
        }
        __syncthreads();
    }

    // epilogue: bias / 2*sigmoid, direct stores to g_om
    int row = pbase + wm*16 + (lane >> 2);
    int col = wn*8 + 2*(lane & 3);
#pragma unroll
    for (int q = 0; q < 4; q++) {
        int cc = col + (q & 1);
        int rr = row + (q >> 1)*8;
        float v = acc[q];
        if (cc < 18)      v = v + off_b[cc];
        else if (cc < 27) v = 2.f / (1.f + expf(-(v + mod_b[cc-18])));
        else continue;
        g_om[rr*32 + cc] = v;
    }
}

// ---------------------------------------------------------------------------
// Kernel 4: deformable conv via mma.sync fp16, full-tap phases (K=256).
// Block: 256 thr = 8 warps (2m x 4n), M=32 pos, N=256. Grid 800. 9 syncs.
// Gather now runs fully in fp16 from g_xph (half traffic, no cvt chain).
// ---------------------------------------------------------------------------
struct DeformSmem {
    __align__(16) char  sU[32768];     // union: A bufs 2x16384 / epi 32K
    __align__(16) uint4  sHW[288];     // corner weights as half2 x4 [tap][pos]
    __align__(16) int4   sCI[288];     // corner POSITION indices
    int   sOB[32];
    float sBias[256];
};

__device__ __forceinline__ void deform_gather(DeformSmem* sm, int tap, int buf,
                                              int t) {
    const uint4* xph4 = (const uint4*)g_xph;
    int p = t >> 3, g = t & 7;
    uint4 hw = sm->sHW[tap*32 + p];
    int4 iv = sm->sCI[tap*32 + p];
    char* Ab = sm->sU + buf*16384;
    int off = p*128 + ((g*16) ^ ((p & 7) << 4));
#pragma unroll
    for (int c4 = 0; c4 < 4; c4++) {
        int e = c4*8 + g;
        uint4 a  = xph4[iv.x*32 + e];
        uint4 b2 = xph4[iv.y*32 + e];
        uint4 c2 = xph4[iv.z*32 + e];
        uint4 d2 = xph4[iv.w*32 + e];
        uint4 r;
        r.x = blend4_h2(a.x, b2.x, c2.x, d2.x, hw.x, hw.y, hw.z, hw.w);
        r.y = blend4_h2(a.y, b2.y, c2.y, d2.y, hw.x, hw.y, hw.z, hw.w);
        r.z = blend4_h2(a.z, b2.z, c2.z, d2.z, hw.x, hw.y, hw.z, hw.w);
        r.w = blend4_h2(a.w, b2.w, c2.w, d2.w, hw.x, hw.y, hw.z, hw.w);
        *(uint4*)(Ab + c4*4096 + off) = r;
    }
}

__global__ void __launch_bounds__(256, 3) deform_kernel(const float* __restrict__ bias,
                                                        float* __restrict__ out) {
    __shared__ DeformSmem sm;
    uint32_t sb = smem_u32(sm.sU);

    int t = threadIdx.x, lane = t & 31, wid = t >> 5;
    int wm = wid >> 2, wn = wid & 3;    // 2m x 4n
    int pbase = blockIdx.x * 32;

    // corners for all 9 taps (288 = 9 x 32)
    for (int q = t; q < 288; q += 256) {
        int tap = q >> 5, p = q & 31;
        int pgl = pbase + p;
        int b = pgl / HW, r = pgl % HW;
        int h = r / WW, w = r % WW;
        float dy = g_om[pgl*32 + 2*tap];
        float dx = g_om[pgl*32 + 2*tap + 1];
        float m  = g_om[pgl*32 + 18 + tap];
        float py = (float)(h - 1 + tap/3) + dy;
        float px = (float)(w - 1 + tap%3) + dx;
        float fy = floorf(py), fx = floorf(px);
        int y0 = (int)fy, x0 = (int)fx;
        float wy = py - fy, wx = px - fx;
        int y1 = y0 + 1, x1 = x0 + 1;
        bool vy0 = (unsigned)y0 < HH, vy1 = (unsigned)y1 < HH;
        bool vx0 = (unsigned)x0 < WW, vx1 = (unsigned)x1 < WW;
        float w00 = (1.f-wy)*(1.f-wx)*m * (float)(vy0 && vx0);
        float w01 = (1.f-wy)*wx      *m * (float)(vy0 && vx1);
        float w10 = wy*(1.f-wx)      *m * (float)(vy1 && vx0);
        float w11 = wy*wx            *m * (float)(vy1 && vx1);
        uint4 hw;
        hw.x = pack_f16(w00, w00);
        hw.y = pack_f16(w01, w01);
        hw.z = pack_f16(w10, w10);
        hw.w = pack_f16(w11, w11);
        int yc0 = min(max(y0, 0), HH-1), yc1 = min(max(y1, 0), HH-1);
        int xc0 = min(max(x0, 0), WW-1), xc1 = min(max(x1, 0), WW-1);
        int rowb = b*HH;
        int4 iv;
        iv.x = (rowb + yc0)*WW + xc0;
        iv.y = (rowb + yc0)*WW + xc1;
        iv.z = (rowb + yc1)*WW + xc0;
        iv.w = (rowb + yc1)*WW + xc1;
        sm.sHW[q] = hw;
        sm.sCI[q] = iv;
    }
    if (t < 32) {
        int pgl = pbase + t;
        sm.sOB[t] = (pgl / HW) * (CC*HW) + (pgl % HW);
    }
    sm.sBias[t] = bias[t];
    __syncthreads();

    deform_gather(&sm, 0, 0, t);
    __syncthreads();

    float acc[8][4];
#pragma unroll
    for (int nt = 0; nt < 8; nt++)
#pragma unroll
        for (int q = 0; q < 4; q++) acc[nt][q] = 0.f;

    int m0 = wm * 16;
    int rowterm = (m0 + (lane & 15)) * 128;
    int kterm = ((lane >> 4) & 1) * 16;
    int swzl = (lane & 7) << 4;

    for (int tap = 0; tap < 9; tap++) {
        int buf = tap & 1;
        if (tap + 1 < 9) deform_gather(&sm, tap + 1, buf ^ 1, t);

#pragma unroll 1
        for (int c4 = 0; c4 < 4; c4++) {
            uint32_t Ah = sb + buf*16384 + c4*4096;
            const uint2* gbase = g_wf + ((size_t)(tap*4 + c4)*4*32 + wn*8) * 32 + lane;
#pragma unroll
            for (int h = 0; h < 4; h++) {
                uint2 bf[8];
#pragma unroll
                for (int nt = 0; nt < 8; nt++)
                    bf[nt] = gbase[(h*32 + nt) * 32];
                int off = (h*32 + kterm) ^ swzl;
                uint32_t a0, a1, a2, a3;
                ldsm4(a0, a1, a2, a3, Ah + rowterm + off);
#pragma unroll
                for (int nt = 0; nt < 8; nt++)
                    mma16816(acc[nt], a0, a1, a2, a3, bf[nt].x, bf[nt].y);
            }
        }
        __syncthreads();
    }

    // epilogue: acc -> smem (reuse A region) -> coalesced NCHW stores
    float* sEp = (float*)sm.sU;   // [o][m] = [256][32]
    int rr = lane >> 2, cc = 2*(lane & 3);
#pragma unroll
    for (int nt = 0; nt < 8; nt++) {
        int n = (wn*8 + nt)*8 + cc;
        int m = m0 + rr;
        sEp[n*32 + m]         = acc[nt][0];
        sEp[(n+1)*32 + m]     = acc[nt][1];
        sEp[n*32 + m + 8]     = acc[nt][2];
        sEp[(n+1)*32 + m + 8] = acc[nt][3];
    }
    __syncthreads();
#pragma unroll
    for (int i = 0; i < 32; i++) {
        int idx = i*256 + t;
        int m = idx & 31, o = idx >> 5;
        out[sm.sOB[m] + o*HW] = sEp[idx] + sm.sBias[o];
    }
}

// ---------------------------------------------------------------------------
extern "C" void kernel_launch(void* const* d_in, const int* in_sizes, int n_in,
                              void* d_out, int out_size) {
    const float* x     = (const float*)d_in[0];
    const float* off_w = (const float*)d_in[1];
    const float* off_b = (const float*)d_in[2];
    const float* mod_w = (const float*)d_in[3];
    const float* mod_b = (const float*)d_in[4];
    const float* w     = (const float*)d_in[5];
    const float* b     = (const float*)d_in[6];
    float* out = (float*)d_out;

    pool_h<<<(NPOS*CC)/256, 256>>>(x);
    pool_v<<<BB*HH*5*16, 256>>>();
    wprep_kernel<<<(NWF + NWFO + 255)/256, 256>>>(off_w, mod_w, w);
    offmask_kernel<<<NPOS/32, 256>>>(off_b, mod_b);
    deform_kernel<<<NPOS/32, 256>>>(b, out);
}